// round 3
// baseline (speedup 1.0000x reference)
#include <cuda_runtime.h>
#include <cuda_bf16.h>
#include <cstdint>

#define BATCH 512
#define NH    50      // history length
#define ED    128     // embed dim
#define HD    200     // hidden dim
#define NE    50000   // num entities
#define KP    208     // K padded to 13*16 for mma

// ---------------- device scratch (allowed: __device__ globals) ----------------
__device__ float          g_c[BATCH * NH];                 // final routing coefficients
__device__ __nv_bfloat16  g_vb[BATCH * KP];                // v (poses) in bf16, K-padded
__device__ __nv_bfloat16  g_Wb[(size_t)NE * KP];           // mlp_w in bf16, K-padded (20.8MB)
__device__ float          g_es[(size_t)BATCH * NE];        // exp(scores) (102.4MB)
__device__ float          g_up[BATCH];                     // uniform p value per row
__device__ float          g_inv[BATCH];                    // 1 / rowsum(exp(scores))
__device__ float          g_pval[BATCH * NH];              // p value per (row, owner-slot), -1 if dup

// ---------------- K0: convert mlp_w f32 -> bf16, pad K to 208 ----------------
__global__ void k_convw(const float* __restrict__ W) {
    int e = blockIdx.x;
    int k = threadIdx.x;
    if (k < KP)
        g_Wb[(size_t)e * KP + k] =
            __float2bfloat16(k < HD ? W[(size_t)e * HD + k] : 0.f);
}

// ---------------- K1: gather + Ws GEMM + normalize + dynamic routing ----------
// One block per batch row. Dynamic shared: Wt[128][201] | Et[128][52] | small arrays.
// Phase 2 reuses the Wt region for X/U (50x200).
__global__ void __launch_bounds__(256) k_routing(
    const int* __restrict__ idx, const int* __restrict__ times,
    const float* __restrict__ emb, const float* __restrict__ Wsw,
    const float* __restrict__ Wsb)
{
    extern __shared__ float sm[];
    const int row  = blockIdx.x;
    const int tid  = threadIdx.x;
    const int lane = tid & 31;
    const int warp = tid >> 5;

    float* Wt = sm;                  // 128*201 = 25728 floats (conflict-free stride 201)
    float* Et = sm + 25728;          // 128*52  = 6656 floats (n padded 50->52 for float4)
    float* X  = sm;                  // phase2: 50*200, overlaps Wt
    const int HB = 32384;
    int*   sidx = (int*)&sm[HB];     // 50
    float* bvec = &sm[HB + 64];      // 50
    float* cvec = &sm[HB + 128];     // 50
    float* vvec = &sm[HB + 192];     // 200
    float* ninv = &sm[HB + 400];     // 50
    float* red  = &sm[HB + 456];     // 256

    // phase 0: row metadata
    if (tid < NH) {
        sidx[tid] = idx[row * NH + tid];
        bvec[tid] = 2.0f / (1.0f + (float)times[row * NH + tid]); // (W+1)/(W+t), W=1
    }
    // stage Ws transposed: Wt[d][h]
    for (int i = tid; i < HD * ED; i += 256) {
        int h = i >> 7, d = i & 127;
        Wt[d * 201 + h] = Wsw[i];
    }
    // zero the n-padding of Et
    for (int d = tid; d < ED; d += 256) {
        Et[d * 52 + 50] = 0.f; Et[d * 52 + 51] = 0.f;
    }
    __syncthreads();
    // gather embeddings transposed: Et[d][n]
    for (int i = tid; i < NH * ED; i += 256) {
        int n = i >> 7, d = i & 127;
        Et[d * 52 + n] = emb[(size_t)sidx[n] * ED + d];
    }
    __syncthreads();

    // phase 1: x[n][h] for h = tid, all n in registers
    float acc[52];
    if (tid < HD) {
        float bias = Wsb[tid];
#pragma unroll
        for (int n = 0; n < 52; ++n) acc[n] = (n < NH) ? bias : 0.f;
        for (int d = 0; d < ED; ++d) {
            float w = Wt[d * 201 + tid];
            const float4* ep = (const float4*)&Et[d * 52];
#pragma unroll
            for (int j = 0; j < 13; ++j) {
                float4 e4 = ep[j];
                acc[4*j+0] = fmaf(e4.x, w, acc[4*j+0]);
                acc[4*j+1] = fmaf(e4.y, w, acc[4*j+1]);
                acc[4*j+2] = fmaf(e4.z, w, acc[4*j+2]);
                acc[4*j+3] = fmaf(e4.w, w, acc[4*j+3]);
            }
        }
    }
    __syncthreads();          // done with Wt/Et; X may overwrite
    if (tid < HD) {
#pragma unroll
        for (int n = 0; n < NH; ++n) X[n * HD + tid] = acc[n];
    }
    __syncthreads();

    // L2 normalize each x[n] over h -> u_hat
    for (int n = warp; n < NH; n += 8) {
        float ss = 0.f;
        for (int h = lane; h < HD; h += 32) { float x = X[n * HD + h]; ss += x * x; }
#pragma unroll
        for (int o = 16; o > 0; o >>= 1) ss += __shfl_xor_sync(0xffffffffu, ss, o);
        if (lane == 0) ninv[n] = 1.0f / fmaxf(sqrtf(ss), 1e-12f);
    }
    __syncthreads();
    if (tid < HD) {
#pragma unroll
        for (int n = 0; n < NH; ++n) X[n * HD + tid] *= ninv[n];
    }
    __syncthreads();

    // dynamic routing: 3 iterations
    float sh = 0.f;
    for (int r = 0; r < 3; ++r) {
        if (warp == 0) {  // softmax over bvec[0..49] * 50
            float x1 = (lane < NH) ? bvec[lane] : -1e30f;
            float x2 = (lane + 32 < NH) ? bvec[lane + 32] : -1e30f;
            float m = fmaxf(x1, x2);
#pragma unroll
            for (int o = 16; o > 0; o >>= 1) m = fmaxf(m, __shfl_xor_sync(0xffffffffu, m, o));
            float e1 = (lane < NH) ? __expf(x1 - m) : 0.f;
            float e2 = (lane + 32 < NH) ? __expf(x2 - m) : 0.f;
            float s = e1 + e2;
#pragma unroll
            for (int o = 16; o > 0; o >>= 1) s += __shfl_xor_sync(0xffffffffu, s, o);
            float inv = (float)NH / s;
            if (lane < NH) cvec[lane] = e1 * inv;
            if (lane + 32 < NH) cvec[lane + 32] = e2 * inv;
        }
        __syncthreads();
        // s[h] = sum_n c[n] * u[n][h]
        sh = 0.f;
        if (tid < HD) {
#pragma unroll 5
            for (int n = 0; n < NH; ++n) sh = fmaf(cvec[n], X[n * HD + tid], sh);
        }
        red[tid] = (tid < HD) ? sh * sh : 0.f;
        __syncthreads();
        for (int s2 = 128; s2 > 0; s2 >>= 1) {
            if (tid < s2) red[tid] += red[tid + s2];
            __syncthreads();
        }
        float sq = red[0];
        float scale = sq / ((1.0f + sq) * sqrtf(sq + 1e-9f));  // squash
        if (tid < HD) vvec[tid] = scale * sh;
        __syncthreads();
        if (r < 2) {  // b[n] += u[n] . v
            for (int n = warp; n < NH; n += 8) {
                float p = 0.f;
                for (int h = lane; h < HD; h += 32) p = fmaf(X[n * HD + h], vvec[h], p);
#pragma unroll
                for (int o = 16; o > 0; o >>= 1) p += __shfl_xor_sync(0xffffffffu, p, o);
                if (lane == 0) bvec[n] += p;
            }
            __syncthreads();
        }
    }

    // outputs
    if (tid < NH) g_c[row * NH + tid] = cvec[tid];
    if (tid < KP)
        g_vb[row * KP + tid] = __float2bfloat16((tid < HD) ? vvec[tid] : 0.f);
}

// ---------------- K2: p-row prep (dedupe scatter + closed-form softmax) -------
__global__ void __launch_bounds__(64) k_pprep(const int* __restrict__ idx)
{
    __shared__ int   sid[64];
    __shared__ float sc[64];
    __shared__ float red[64];
    int row = blockIdx.x, tid = threadIdx.x;
    if (tid < NH) { sid[tid] = idx[row * NH + tid]; sc[tid] = g_c[row * NH + tid]; }
    __syncthreads();
    bool owner = false; float csum = 0.f;
    if (tid < NH) {
        int e = sid[tid]; owner = true;
        for (int k = 0; k < NH; ++k)
            if (sid[k] == e) { if (k < tid) owner = false; csum += sc[k]; }
    }
    // pmax over owner csums (all > 0, so equals row max of p)
    red[tid] = (tid < NH && owner) ? csum : -1e30f;
    __syncthreads();
    for (int s = 32; s > 0; s >>= 1) { if (tid < s) red[tid] = fmaxf(red[tid], red[tid + s]); __syncthreads(); }
    float pmax = red[0];
    __syncthreads();
    red[tid] = (tid < NH && owner) ? __expf(csum - pmax) : 0.f;
    __syncthreads();
    for (int s = 32; s > 0; s >>= 1) { if (tid < s) red[tid] += red[tid + s]; __syncthreads(); }
    float s1 = red[0];
    __syncthreads();
    red[tid] = (tid < NH && owner) ? 1.f : 0.f;
    __syncthreads();
    for (int s = 32; s > 0; s >>= 1) { if (tid < s) red[tid] += red[tid + s]; __syncthreads(); }
    float dcount = red[0];
    float eneg   = __expf(-pmax);
    float denom  = s1 + ((float)NE - dcount) * eneg;
    if (tid == 0)  g_up[row] = eneg / denom;
    if (tid < NH)  g_pval[row * NH + tid] = owner ? (__expf(csum - pmax) / denom) : -1.0f;
}

// ---------------- K3: scores GEMM (bf16 mma.sync, fp32 accum) -> exp(score) ---
// block tile 128m x 64n, 8 warps (2m x 4n), warp tile 64m x 16n, K loop 13x16.
__global__ void __launch_bounds__(256) k_gemm(const float* __restrict__ bias)
{
    const int tid  = threadIdx.x;
    const int warp = tid >> 5, lane = tid & 31;
    const int g = lane >> 2, t = lane & 3;
    const int mw = warp >> 2, nw = warp & 3;
    const int mbase = blockIdx.y * 128 + mw * 64;
    const int ebase = blockIdx.x * 64  + nw * 16;

    float acc[4][2][4];
#pragma unroll
    for (int a = 0; a < 4; a++)
#pragma unroll
        for (int b = 0; b < 2; b++)
#pragma unroll
            for (int c = 0; c < 4; c++) acc[a][b][c] = 0.f;

    for (int kc = 0; kc < 13; ++kc) {
        const int k0 = kc * 16;
        uint32_t bf[2][2];
#pragma unroll
        for (int nt = 0; nt < 2; ++nt) {
            int e = ebase + nt * 8 + g;
            if (e < NE) {
                const __nv_bfloat16* wp = g_Wb + (size_t)e * KP + k0 + 2 * t;
                bf[nt][0] = *(const uint32_t*)wp;
                bf[nt][1] = *(const uint32_t*)(wp + 8);
            } else { bf[nt][0] = 0u; bf[nt][1] = 0u; }
        }
#pragma unroll
        for (int mt = 0; mt < 4; ++mt) {
            const __nv_bfloat16* ap = g_vb + (size_t)(mbase + mt * 16 + g) * KP + k0 + 2 * t;
            uint32_t a0 = *(const uint32_t*)ap;
            uint32_t a1 = *(const uint32_t*)(ap + 8 * KP);
            uint32_t a2 = *(const uint32_t*)(ap + 8);
            uint32_t a3 = *(const uint32_t*)(ap + 8 * KP + 8);
#pragma unroll
            for (int nt = 0; nt < 2; ++nt) {
                asm volatile(
                    "mma.sync.aligned.m16n8k16.row.col.f32.bf16.bf16.f32 "
                    "{%0,%1,%2,%3}, {%4,%5,%6,%7}, {%8,%9}, {%0,%1,%2,%3};\n"
                    : "+f"(acc[mt][nt][0]), "+f"(acc[mt][nt][1]),
                      "+f"(acc[mt][nt][2]), "+f"(acc[mt][nt][3])
                    : "r"(a0), "r"(a1), "r"(a2), "r"(a3),
                      "r"(bf[nt][0]), "r"(bf[nt][1]));
            }
        }
    }
    // epilogue: exp(score + bias) -> scratch (|score|<0.2 so no max-sub needed)
#pragma unroll
    for (int mt = 0; mt < 4; ++mt) {
        int r0 = mbase + mt * 16 + g;
#pragma unroll
        for (int nt = 0; nt < 2; ++nt) {
            int e0 = ebase + nt * 8 + 2 * t;
            if (e0 < NE) {
                float b0v = bias[e0], b1v = bias[e0 + 1];
                float2 u = make_float2(__expf(acc[mt][nt][0] + b0v),
                                       __expf(acc[mt][nt][1] + b1v));
                float2 l = make_float2(__expf(acc[mt][nt][2] + b0v),
                                       __expf(acc[mt][nt][3] + b1v));
                *(float2*)&g_es[(size_t)r0 * NE + e0]       = u;
                *(float2*)&g_es[(size_t)(r0 + 8) * NE + e0] = l;
            }
        }
    }
}

// ---------------- K3b: deterministic row sums of exp(scores) ------------------
__global__ void __launch_bounds__(256) k_rowsum()
{
    __shared__ float red[256];
    int row = blockIdx.x, tid = threadIdx.x;
    const float* p = g_es + (size_t)row * NE;
    float s = 0.f;
    for (int e = tid * 4; e < NE; e += 256 * 4) {
        float4 v = *(const float4*)(p + e);
        s += (v.x + v.y) + (v.z + v.w);
    }
    red[tid] = s; __syncthreads();
    for (int st = 128; st > 0; st >>= 1) {
        if (tid < st) red[tid] += red[tid + st];
        __syncthreads();
    }
    if (tid == 0) g_inv[row] = 1.0f / red[0];
}

// ---------------- K4: out = log(0.5*p_uniform + 0.5*sims) ---------------------
__global__ void __launch_bounds__(256) k_final(float* __restrict__ out)
{
    size_t i = (size_t)blockIdx.x * blockDim.x + threadIdx.x;   // float4 index
    int row = (int)(i / (NE / 4));
    float up  = 0.5f * g_up[row];
    float inv = 0.5f * g_inv[row];
    float4 v = *((const float4*)g_es + i);
    float4 o;
    o.x = __logf(fmaf(v.x, inv, up));
    o.y = __logf(fmaf(v.y, inv, up));
    o.z = __logf(fmaf(v.z, inv, up));
    o.w = __logf(fmaf(v.w, inv, up));
    ((float4*)out)[i] = o;
}

// ---------------- K5: fixup the <=50 scattered-p entries per row --------------
__global__ void __launch_bounds__(64) k_fix(const int* __restrict__ idx,
                                            float* __restrict__ out)
{
    int row = blockIdx.x, tid = threadIdx.x;
    if (tid < NH) {
        float pv = g_pval[row * NH + tid];
        if (pv >= 0.f) {
            int e = idx[row * NH + tid];
            float es = g_es[(size_t)row * NE + e];
            out[(size_t)row * NE + e] = __logf(0.5f * pv + 0.5f * es * g_inv[row]);
        }
    }
}

// ---------------- launch ------------------------------------------------------
extern "C" void kernel_launch(void* const* d_in, const int* in_sizes, int n_in,
                              void* d_out, int out_size)
{
    const int*   idx   = (const int*)d_in[0];
    const int*   times = (const int*)d_in[1];
    const float* emb   = (const float*)d_in[2];
    const float* Wsw   = (const float*)d_in[3];
    const float* Wsb   = (const float*)d_in[4];
    const float* mlpw  = (const float*)d_in[5];
    const float* mlpb  = (const float*)d_in[6];
    float*       out   = (float*)d_out;

    cudaFuncSetAttribute(k_routing, cudaFuncAttributeMaxDynamicSharedMemorySize, 139264);

    k_convw  <<<NE, 256>>>(mlpw);
    k_routing<<<BATCH, 256, 132384>>>(idx, times, emb, Wsw, Wsb);
    k_pprep  <<<BATCH, 64>>>(idx);
    k_gemm   <<<dim3((NE + 63) / 64, BATCH / 128), 256>>>(mlpb);
    k_rowsum <<<BATCH, 256>>>();
    k_final  <<<(BATCH * NE / 4) / 256, 256>>>(out);   // 25000 blocks, exact cover
    k_fix    <<<BATCH, 64>>>(idx, out);
}

// round 7
// speedup vs baseline: 1.0076x; 1.0076x over previous
#include <cuda_runtime.h>
#include <cuda_bf16.h>
#include <cstdint>

#define BATCH 512
#define NH    50      // history length
#define ED    128     // embed dim
#define HD    200     // hidden dim
#define NE    50000   // num entities
#define KP    208     // K padded to 13*16 for mma

// ---------------- device scratch (allowed: __device__ globals) ----------------
__device__ float          g_c[BATCH * NH];                 // final routing coefficients
__device__ __nv_bfloat16  g_vb[BATCH * KP];                // v (poses) in bf16, K-padded
__device__ __nv_bfloat16  g_Wb[(size_t)NE * KP];           // mlp_w in bf16, K-padded (20.8MB)
__device__ float          g_es[(size_t)BATCH * NE];        // exp(scores) (102.4MB)
__device__ float          g_up[BATCH];                     // uniform p value per row
__device__ float          g_inv[BATCH];                    // 1 / rowsum(exp(scores))
__device__ float          g_pval[BATCH * NH];              // p value per (row, owner-slot), -1 if dup

// ---------------- K0: convert mlp_w f32 -> bf16, pad K to 208 ----------------
__global__ void k_convw(const float* __restrict__ W) {
    int e = blockIdx.x;
    int k = threadIdx.x;
    if (k < KP)
        g_Wb[(size_t)e * KP + k] =
            __float2bfloat16(k < HD ? W[(size_t)e * HD + k] : 0.f);
}

// ---------------- K1: gather + Ws GEMM + normalize + dynamic routing ----------
// One block per batch row. Dynamic shared: Wt[128][201] | Et[128][52] | small arrays.
// Phase 2 reuses the Wt region for X/U (50x200).
__global__ void __launch_bounds__(256) k_routing(
    const int* __restrict__ idx, const int* __restrict__ times,
    const float* __restrict__ emb, const float* __restrict__ Wsw,
    const float* __restrict__ Wsb)
{
    extern __shared__ float sm[];
    const int row  = blockIdx.x;
    const int tid  = threadIdx.x;
    const int lane = tid & 31;
    const int warp = tid >> 5;

    float* Wt = sm;                  // 128*201 = 25728 floats (conflict-free stride 201)
    float* Et = sm + 25728;          // 128*52  = 6656 floats (n padded 50->52 for float4)
    float* X  = sm;                  // phase2: 50*200, overlaps Wt
    const int HB = 32384;
    int*   sidx = (int*)&sm[HB];     // 50
    float* bvec = &sm[HB + 64];      // 50
    float* cvec = &sm[HB + 128];     // 50
    float* vvec = &sm[HB + 192];     // 200
    float* ninv = &sm[HB + 400];     // 50
    float* red  = &sm[HB + 456];     // 256

    // phase 0: row metadata
    if (tid < NH) {
        sidx[tid] = idx[row * NH + tid];
        bvec[tid] = 2.0f / (1.0f + (float)times[row * NH + tid]); // (W+1)/(W+t), W=1
    }
    // stage Ws transposed: Wt[d][h]
    for (int i = tid; i < HD * ED; i += 256) {
        int h = i >> 7, d = i & 127;
        Wt[d * 201 + h] = Wsw[i];
    }
    // zero the n-padding of Et
    for (int d = tid; d < ED; d += 256) {
        Et[d * 52 + 50] = 0.f; Et[d * 52 + 51] = 0.f;
    }
    __syncthreads();
    // gather embeddings transposed: Et[d][n]
    for (int i = tid; i < NH * ED; i += 256) {
        int n = i >> 7, d = i & 127;
        Et[d * 52 + n] = emb[(size_t)sidx[n] * ED + d];
    }
    __syncthreads();

    // phase 1: x[n][h] for h = tid, all n in registers
    float acc[52];
    if (tid < HD) {
        float bias = Wsb[tid];
#pragma unroll
        for (int n = 0; n < 52; ++n) acc[n] = (n < NH) ? bias : 0.f;
        for (int d = 0; d < ED; ++d) {
            float w = Wt[d * 201 + tid];
            const float4* ep = (const float4*)&Et[d * 52];
#pragma unroll
            for (int j = 0; j < 13; ++j) {
                float4 e4 = ep[j];
                acc[4*j+0] = fmaf(e4.x, w, acc[4*j+0]);
                acc[4*j+1] = fmaf(e4.y, w, acc[4*j+1]);
                acc[4*j+2] = fmaf(e4.z, w, acc[4*j+2]);
                acc[4*j+3] = fmaf(e4.w, w, acc[4*j+3]);
            }
        }
    }
    __syncthreads();          // done with Wt/Et; X may overwrite
    if (tid < HD) {
#pragma unroll
        for (int n = 0; n < NH; ++n) X[n * HD + tid] = acc[n];
    }
    __syncthreads();

    // L2 normalize each x[n] over h -> u_hat
    for (int n = warp; n < NH; n += 8) {
        float ss = 0.f;
        for (int h = lane; h < HD; h += 32) { float x = X[n * HD + h]; ss += x * x; }
#pragma unroll
        for (int o = 16; o > 0; o >>= 1) ss += __shfl_xor_sync(0xffffffffu, ss, o);
        if (lane == 0) ninv[n] = 1.0f / fmaxf(sqrtf(ss), 1e-12f);
    }
    __syncthreads();
    if (tid < HD) {
#pragma unroll
        for (int n = 0; n < NH; ++n) X[n * HD + tid] *= ninv[n];
    }
    __syncthreads();

    // dynamic routing: 3 iterations
    float sh = 0.f;
    for (int r = 0; r < 3; ++r) {
        if (warp == 0) {  // softmax over bvec[0..49] * 50
            float x1 = (lane < NH) ? bvec[lane] : -1e30f;
            float x2 = (lane + 32 < NH) ? bvec[lane + 32] : -1e30f;
            float m = fmaxf(x1, x2);
#pragma unroll
            for (int o = 16; o > 0; o >>= 1) m = fmaxf(m, __shfl_xor_sync(0xffffffffu, m, o));
            float e1 = (lane < NH) ? __expf(x1 - m) : 0.f;
            float e2 = (lane + 32 < NH) ? __expf(x2 - m) : 0.f;
            float s = e1 + e2;
#pragma unroll
            for (int o = 16; o > 0; o >>= 1) s += __shfl_xor_sync(0xffffffffu, s, o);
            float inv = (float)NH / s;
            if (lane < NH) cvec[lane] = e1 * inv;
            if (lane + 32 < NH) cvec[lane + 32] = e2 * inv;
        }
        __syncthreads();
        // s[h] = sum_n c[n] * u[n][h]
        sh = 0.f;
        if (tid < HD) {
#pragma unroll 5
            for (int n = 0; n < NH; ++n) sh = fmaf(cvec[n], X[n * HD + tid], sh);
        }
        red[tid] = (tid < HD) ? sh * sh : 0.f;
        __syncthreads();
        for (int s2 = 128; s2 > 0; s2 >>= 1) {
            if (tid < s2) red[tid] += red[tid + s2];
            __syncthreads();
        }
        float sq = red[0];
        float scale = sq / ((1.0f + sq) * sqrtf(sq + 1e-9f));  // squash
        if (tid < HD) vvec[tid] = scale * sh;
        __syncthreads();
        if (r < 2) {  // b[n] += u[n] . v
            for (int n = warp; n < NH; n += 8) {
                float p = 0.f;
                for (int h = lane; h < HD; h += 32) p = fmaf(X[n * HD + h], vvec[h], p);
#pragma unroll
                for (int o = 16; o > 0; o >>= 1) p += __shfl_xor_sync(0xffffffffu, p, o);
                if (lane == 0) bvec[n] += p;
            }
            __syncthreads();
        }
    }

    // outputs
    if (tid < NH) g_c[row * NH + tid] = cvec[tid];
    if (tid < KP)
        g_vb[row * KP + tid] = __float2bfloat16((tid < HD) ? vvec[tid] : 0.f);
}

// ---------------- K2: p-row prep (dedupe scatter + closed-form softmax) -------
__global__ void __launch_bounds__(64) k_pprep(const int* __restrict__ idx)
{
    __shared__ int   sid[64];
    __shared__ float sc[64];
    __shared__ float red[64];
    int row = blockIdx.x, tid = threadIdx.x;
    if (tid < NH) { sid[tid] = idx[row * NH + tid]; sc[tid] = g_c[row * NH + tid]; }
    __syncthreads();
    bool owner = false; float csum = 0.f;
    if (tid < NH) {
        int e = sid[tid]; owner = true;
        for (int k = 0; k < NH; ++k)
            if (sid[k] == e) { if (k < tid) owner = false; csum += sc[k]; }
    }
    // pmax over owner csums (all > 0, so equals row max of p)
    red[tid] = (tid < NH && owner) ? csum : -1e30f;
    __syncthreads();
    for (int s = 32; s > 0; s >>= 1) { if (tid < s) red[tid] = fmaxf(red[tid], red[tid + s]); __syncthreads(); }
    float pmax = red[0];
    __syncthreads();
    red[tid] = (tid < NH && owner) ? __expf(csum - pmax) : 0.f;
    __syncthreads();
    for (int s = 32; s > 0; s >>= 1) { if (tid < s) red[tid] += red[tid + s]; __syncthreads(); }
    float s1 = red[0];
    __syncthreads();
    red[tid] = (tid < NH && owner) ? 1.f : 0.f;
    __syncthreads();
    for (int s = 32; s > 0; s >>= 1) { if (tid < s) red[tid] += red[tid + s]; __syncthreads(); }
    float dcount = red[0];
    float eneg   = __expf(-pmax);
    float denom  = s1 + ((float)NE - dcount) * eneg;
    if (tid == 0)  g_up[row] = eneg / denom;
    if (tid < NH)  g_pval[row * NH + tid] = owner ? (__expf(csum - pmax) / denom) : -1.0f;
}

// ---------------- K3: scores GEMM (bf16 mma.sync, fp32 accum) -> exp(score) ---
// block tile 128m x 64n, 8 warps (2m x 4n), warp tile 64m x 16n, K loop 13x16.
__global__ void __launch_bounds__(256) k_gemm(const float* __restrict__ bias)
{
    const int tid  = threadIdx.x;
    const int warp = tid >> 5, lane = tid & 31;
    const int g = lane >> 2, t = lane & 3;
    const int mw = warp >> 2, nw = warp & 3;
    const int mbase = blockIdx.y * 128 + mw * 64;
    const int ebase = blockIdx.x * 64  + nw * 16;

    float acc[4][2][4];
#pragma unroll
    for (int a = 0; a < 4; a++)
#pragma unroll
        for (int b = 0; b < 2; b++)
#pragma unroll
            for (int c = 0; c < 4; c++) acc[a][b][c] = 0.f;

    for (int kc = 0; kc < 13; ++kc) {
        const int k0 = kc * 16;
        uint32_t bf[2][2];
#pragma unroll
        for (int nt = 0; nt < 2; ++nt) {
            int e = ebase + nt * 8 + g;
            if (e < NE) {
                const __nv_bfloat16* wp = g_Wb + (size_t)e * KP + k0 + 2 * t;
                bf[nt][0] = *(const uint32_t*)wp;
                bf[nt][1] = *(const uint32_t*)(wp + 8);
            } else { bf[nt][0] = 0u; bf[nt][1] = 0u; }
        }
#pragma unroll
        for (int mt = 0; mt < 4; ++mt) {
            const __nv_bfloat16* ap = g_vb + (size_t)(mbase + mt * 16 + g) * KP + k0 + 2 * t;
            uint32_t a0 = *(const uint32_t*)ap;
            uint32_t a1 = *(const uint32_t*)(ap + 8 * KP);
            uint32_t a2 = *(const uint32_t*)(ap + 8);
            uint32_t a3 = *(const uint32_t*)(ap + 8 * KP + 8);
#pragma unroll
            for (int nt = 0; nt < 2; ++nt) {
                asm volatile(
                    "mma.sync.aligned.m16n8k16.row.col.f32.bf16.bf16.f32 "
                    "{%0,%1,%2,%3}, {%4,%5,%6,%7}, {%8,%9}, {%0,%1,%2,%3};\n"
                    : "+f"(acc[mt][nt][0]), "+f"(acc[mt][nt][1]),
                      "+f"(acc[mt][nt][2]), "+f"(acc[mt][nt][3])
                    : "r"(a0), "r"(a1), "r"(a2), "r"(a3),
                      "r"(bf[nt][0]), "r"(bf[nt][1]));
            }
        }
    }
    // epilogue: exp(score + bias) -> scratch (|score|<0.2 so no max-sub needed)
#pragma unroll
    for (int mt = 0; mt < 4; ++mt) {
        int r0 = mbase + mt * 16 + g;
#pragma unroll
        for (int nt = 0; nt < 2; ++nt) {
            int e0 = ebase + nt * 8 + 2 * t;
            if (e0 < NE) {
                float b0v = bias[e0], b1v = bias[e0 + 1];
                float2 u = make_float2(__expf(acc[mt][nt][0] + b0v),
                                       __expf(acc[mt][nt][1] + b1v));
                float2 l = make_float2(__expf(acc[mt][nt][2] + b0v),
                                       __expf(acc[mt][nt][3] + b1v));
                *(float2*)&g_es[(size_t)r0 * NE + e0]       = u;
                *(float2*)&g_es[(size_t)(r0 + 8) * NE + e0] = l;
            }
        }
    }
}

// ---------------- K3b: deterministic row sums of exp(scores) ------------------
__global__ void __launch_bounds__(256) k_rowsum()
{
    __shared__ float red[256];
    int row = blockIdx.x, tid = threadIdx.x;
    const float* p = g_es + (size_t)row * NE;
    float s = 0.f;
    for (int e = tid * 4; e < NE; e += 256 * 4) {
        float4 v = *(const float4*)(p + e);
        s += (v.x + v.y) + (v.z + v.w);
    }
    red[tid] = s; __syncthreads();
    for (int st = 128; st > 0; st >>= 1) {
        if (tid < st) red[tid] += red[tid + st];
        __syncthreads();
    }
    if (tid == 0) g_inv[row] = 1.0f / red[0];
}

// ---------------- K4: out = log(0.5*p_uniform + 0.5*sims) ---------------------
__global__ void __launch_bounds__(256) k_final(float* __restrict__ out)
{
    size_t i = (size_t)blockIdx.x * blockDim.x + threadIdx.x;   // float4 index
    int row = (int)(i / (NE / 4));
    float up  = 0.5f * g_up[row];
    float inv = 0.5f * g_inv[row];
    float4 v = *((const float4*)g_es + i);
    float4 o;
    o.x = __logf(fmaf(v.x, inv, up));
    o.y = __logf(fmaf(v.y, inv, up));
    o.z = __logf(fmaf(v.z, inv, up));
    o.w = __logf(fmaf(v.w, inv, up));
    ((float4*)out)[i] = o;
}

// ---------------- K5: fixup the <=50 scattered-p entries per row --------------
__global__ void __launch_bounds__(64) k_fix(const int* __restrict__ idx,
                                            float* __restrict__ out)
{
    int row = blockIdx.x, tid = threadIdx.x;
    if (tid < NH) {
        float pv = g_pval[row * NH + tid];
        if (pv >= 0.f) {
            int e = idx[row * NH + tid];
            float es = g_es[(size_t)row * NE + e];
            out[(size_t)row * NE + e] = __logf(0.5f * pv + 0.5f * es * g_inv[row]);
        }
    }
}

// ---------------- launch ------------------------------------------------------
extern "C" void kernel_launch(void* const* d_in, const int* in_sizes, int n_in,
                              void* d_out, int out_size)
{
    const int*   idx   = (const int*)d_in[0];
    const int*   times = (const int*)d_in[1];
    const float* emb   = (const float*)d_in[2];
    const float* Wsw   = (const float*)d_in[3];
    const float* Wsb   = (const float*)d_in[4];
    const float* mlpw  = (const float*)d_in[5];
    const float* mlpb  = (const float*)d_in[6];
    float*       out   = (float*)d_out;

    cudaFuncSetAttribute(k_routing, cudaFuncAttributeMaxDynamicSharedMemorySize, 139264);

    k_convw  <<<NE, 256>>>(mlpw);
    k_routing<<<BATCH, 256, 132384>>>(idx, times, emb, Wsw, Wsb);
    k_pprep  <<<BATCH, 64>>>(idx);
    k_gemm   <<<dim3((NE + 63) / 64, BATCH / 128), 256>>>(mlpb);
    k_rowsum <<<BATCH, 256>>>();
    k_final  <<<(BATCH * NE / 4) / 256, 256>>>(out);   // 25000 blocks, exact cover
    k_fix    <<<BATCH, 64>>>(idx, out);
}

// round 8
// speedup vs baseline: 1.3610x; 1.3507x over previous
#include <cuda_runtime.h>
#include <cuda_bf16.h>
#include <cstdint>

#define BATCH 512
#define NH    50      // history length
#define ED    128     // embed dim
#define HD    200     // hidden dim
#define NE    50000   // num entities
#define KP    208     // K padded to 13*16 for mma
#define GX    391     // gemm grid x (ceil(NE/128))

// ---------------- device scratch (allowed: __device__ globals) ----------------
__device__ float          g_c[BATCH * NH];                 // final routing coefficients
__device__ __nv_bfloat16  g_vb[BATCH * KP];                // v (poses) in bf16, K-padded
__device__ __nv_bfloat16  g_Wb[(size_t)NE * KP];           // mlp_w in bf16, K-padded (20.8MB)
__device__ float          g_es[(size_t)BATCH * NE];        // exp(scores) (102.4MB)
__device__ float          g_up[BATCH];                     // uniform p value per row
__device__ float          g_inv[BATCH];                    // 1 / rowsum(exp(scores))
__device__ float          g_pval[BATCH * NH];              // p value per (row, owner-slot), -1 if dup
__device__ float          g_part[(size_t)BATCH * GX];      // per-block row partial sums

// ---------------- K0: convert mlp_w f32 -> bf16, pad K to 208 ----------------
__global__ void k_convw(const float* __restrict__ W) {
    int e = blockIdx.x;
    int k = threadIdx.x;
    if (k < KP)
        g_Wb[(size_t)e * KP + k] =
            __float2bfloat16(k < HD ? W[(size_t)e * HD + k] : 0.f);
}

// ---------------- K1: gather + Ws GEMM + normalize + dynamic routing ----------
// One block per batch row. Ws staged in d-chunks of 32 so smem = 55KB -> 3 CTAs/SM.
// Word layout: Et[128][52] @0 | Wtc[32][201] @6656 | X[50][200] @0 (phase2 overlap)
// small arrays @13088+. Total 13824 words = 55296 B.
__global__ void __launch_bounds__(256, 3) k_routing(
    const int* __restrict__ idx, const int* __restrict__ times,
    const float* __restrict__ emb, const float* __restrict__ Wsw,
    const float* __restrict__ Wsb)
{
    extern __shared__ float sm[];
    const int row  = blockIdx.x;
    const int tid  = threadIdx.x;
    const int lane = tid & 31;
    const int warp = tid >> 5;

    float* Et  = sm;                 // 128*52 = 6656 words (n padded 50->52 for float4)
    float* Wtc = sm + 6656;          // 32*201 = 6432 words (chunked Ws^T, stride 201)
    float* X   = sm;                 // phase2: 50*200 = 10000 words, overlaps Et/Wtc
    int*   sidx = (int*)&sm[13088];  // 50
    float* bvec = &sm[13152];        // 50
    float* cvec = &sm[13216];        // 50
    float* vvec = &sm[13280];        // 200
    float* ninv = &sm[13504];        // 50
    float* red  = &sm[13568];        // 256

    // phase 0: row metadata
    if (tid < NH) {
        sidx[tid] = idx[row * NH + tid];
        bvec[tid] = 2.0f / (1.0f + (float)times[row * NH + tid]); // (W+1)/(W+t), W=1
    }
    // zero the n-padding of Et
    for (int d = tid; d < ED; d += 256) {
        Et[d * 52 + 50] = 0.f; Et[d * 52 + 51] = 0.f;
    }
    __syncthreads();
    // gather embeddings transposed: Et[d][n]
    for (int i = tid; i < NH * ED; i += 256) {
        int n = i >> 7, d = i & 127;
        Et[d * 52 + n] = emb[(size_t)sidx[n] * ED + d];
    }

    // phase 1: x[n][h] for h = tid, all n in registers; Ws staged in 4 d-chunks
    float acc[52];
    if (tid < HD) {
        float bias = Wsb[tid];
#pragma unroll
        for (int n = 0; n < 52; ++n) acc[n] = (n < NH) ? bias : 0.f;
    }
    for (int c = 0; c < 4; ++c) {
        __syncthreads();   // prev-chunk compute done (and Et gather done at c=0)
        for (int i = tid; i < 32 * HD; i += 256) {
            int h = i >> 5, dd = i & 31;
            Wtc[dd * 201 + h] = Wsw[h * ED + (c << 5) + dd];
        }
        __syncthreads();
        if (tid < HD) {
            for (int dd = 0; dd < 32; ++dd) {
                float w = Wtc[dd * 201 + tid];
                const float4* ep = (const float4*)&Et[((c << 5) + dd) * 52];
#pragma unroll
                for (int j = 0; j < 13; ++j) {
                    float4 e4 = ep[j];
                    acc[4*j+0] = fmaf(e4.x, w, acc[4*j+0]);
                    acc[4*j+1] = fmaf(e4.y, w, acc[4*j+1]);
                    acc[4*j+2] = fmaf(e4.z, w, acc[4*j+2]);
                    acc[4*j+3] = fmaf(e4.w, w, acc[4*j+3]);
                }
            }
        }
    }
    __syncthreads();          // done with Et/Wtc; X may overwrite
    if (tid < HD) {
#pragma unroll
        for (int n = 0; n < NH; ++n) X[n * HD + tid] = acc[n];
    }
    __syncthreads();

    // L2 normalize each x[n] over h -> u_hat
    for (int n = warp; n < NH; n += 8) {
        float ss = 0.f;
        for (int h = lane; h < HD; h += 32) { float x = X[n * HD + h]; ss += x * x; }
#pragma unroll
        for (int o = 16; o > 0; o >>= 1) ss += __shfl_xor_sync(0xffffffffu, ss, o);
        if (lane == 0) ninv[n] = 1.0f / fmaxf(sqrtf(ss), 1e-12f);
    }
    __syncthreads();
    if (tid < HD) {
#pragma unroll
        for (int n = 0; n < NH; ++n) X[n * HD + tid] *= ninv[n];
    }
    __syncthreads();

    // dynamic routing: 3 iterations
    float sh = 0.f;
    for (int r = 0; r < 3; ++r) {
        if (warp == 0) {  // softmax over bvec[0..49] * 50
            float x1 = (lane < NH) ? bvec[lane] : -1e30f;
            float x2 = (lane + 32 < NH) ? bvec[lane + 32] : -1e30f;
            float m = fmaxf(x1, x2);
#pragma unroll
            for (int o = 16; o > 0; o >>= 1) m = fmaxf(m, __shfl_xor_sync(0xffffffffu, m, o));
            float e1 = (lane < NH) ? __expf(x1 - m) : 0.f;
            float e2 = (lane + 32 < NH) ? __expf(x2 - m) : 0.f;
            float s = e1 + e2;
#pragma unroll
            for (int o = 16; o > 0; o >>= 1) s += __shfl_xor_sync(0xffffffffu, s, o);
            float inv = (float)NH / s;
            if (lane < NH) cvec[lane] = e1 * inv;
            if (lane + 32 < NH) cvec[lane + 32] = e2 * inv;
        }
        __syncthreads();
        // s[h] = sum_n c[n] * u[n][h]
        sh = 0.f;
        if (tid < HD) {
#pragma unroll 5
            for (int n = 0; n < NH; ++n) sh = fmaf(cvec[n], X[n * HD + tid], sh);
        }
        red[tid] = (tid < HD) ? sh * sh : 0.f;
        __syncthreads();
        for (int s2 = 128; s2 > 0; s2 >>= 1) {
            if (tid < s2) red[tid] += red[tid + s2];
            __syncthreads();
        }
        float sq = red[0];
        float scale = sq / ((1.0f + sq) * sqrtf(sq + 1e-9f));  // squash
        if (tid < HD) vvec[tid] = scale * sh;
        __syncthreads();
        if (r < 2) {  // b[n] += u[n] . v
            for (int n = warp; n < NH; n += 8) {
                float p = 0.f;
                for (int h = lane; h < HD; h += 32) p = fmaf(X[n * HD + h], vvec[h], p);
#pragma unroll
                for (int o = 16; o > 0; o >>= 1) p += __shfl_xor_sync(0xffffffffu, p, o);
                if (lane == 0) bvec[n] += p;
            }
            __syncthreads();
        }
    }

    // outputs
    if (tid < NH) g_c[row * NH + tid] = cvec[tid];
    if (tid < KP)
        g_vb[row * KP + tid] = __float2bfloat16((tid < HD) ? vvec[tid] : 0.f);
}

// ---------------- K2: p-row prep (dedupe scatter + closed-form softmax) -------
__global__ void __launch_bounds__(64) k_pprep(const int* __restrict__ idx)
{
    __shared__ int   sid[64];
    __shared__ float sc[64];
    __shared__ float red[64];
    int row = blockIdx.x, tid = threadIdx.x;
    if (tid < NH) { sid[tid] = idx[row * NH + tid]; sc[tid] = g_c[row * NH + tid]; }
    __syncthreads();
    bool owner = false; float csum = 0.f;
    if (tid < NH) {
        int e = sid[tid]; owner = true;
        for (int k = 0; k < NH; ++k)
            if (sid[k] == e) { if (k < tid) owner = false; csum += sc[k]; }
    }
    red[tid] = (tid < NH && owner) ? csum : -1e30f;
    __syncthreads();
    for (int s = 32; s > 0; s >>= 1) { if (tid < s) red[tid] = fmaxf(red[tid], red[tid + s]); __syncthreads(); }
    float pmax = red[0];
    __syncthreads();
    red[tid] = (tid < NH && owner) ? __expf(csum - pmax) : 0.f;
    __syncthreads();
    for (int s = 32; s > 0; s >>= 1) { if (tid < s) red[tid] += red[tid + s]; __syncthreads(); }
    float s1 = red[0];
    __syncthreads();
    red[tid] = (tid < NH && owner) ? 1.f : 0.f;
    __syncthreads();
    for (int s = 32; s > 0; s >>= 1) { if (tid < s) red[tid] += red[tid + s]; __syncthreads(); }
    float dcount = red[0];
    float eneg   = __expf(-pmax);
    float denom  = s1 + ((float)NE - dcount) * eneg;
    if (tid == 0)  g_up[row] = eneg / denom;
    if (tid < NH)  g_pval[row * NH + tid] = owner ? (__expf(csum - pmax) / denom) : -1.0f;
}

// ---------------- K3: scores GEMM (bf16 mma.sync, fp32 accum, smem-staged) ----
// block tile 128m x 128n, 8 warps (2m x 4n), warp tile 64m x 32n, K = 13x16.
// A/B staged in smem (stride 216 bf16 = conflict-free for frag reads).
// Epilogue: exp(score+bias) -> g_es, deterministic per-block row sums -> g_part.
__global__ void __launch_bounds__(256, 2) k_gemm(const float* __restrict__ bias)
{
    extern __shared__ char smem_raw[];
    __nv_bfloat16* sA = (__nv_bfloat16*)smem_raw;             // 128 x 216 = 55296 B
    __nv_bfloat16* sB = (__nv_bfloat16*)(smem_raw + 55296);   // 128 x 216 = 55296 B
    float* s_part = (float*)(smem_raw + 110592);              // [4][128]

    const int tid  = threadIdx.x;
    const int warp = tid >> 5, lane = tid & 31;
    const int g = lane >> 2, t = lane & 3;
    const int mw = warp >> 2, nw = warp & 3;
    const int mblk = blockIdx.y * 128;
    const int eblk = blockIdx.x * 128;

    // stage A (always-valid rows) and B (guard e < NE), 26 uint4 per 208-col row
    for (int i = tid; i < 128 * 26; i += 256) {
        int r = i / 26, c8 = i % 26;
        uint4 v = *(const uint4*)&g_vb[(size_t)(mblk + r) * KP + c8 * 8];
        *(uint4*)&sA[r * 216 + c8 * 8] = v;
    }
    for (int i = tid; i < 128 * 26; i += 256) {
        int r = i / 26, c8 = i % 26;
        int e = eblk + r;
        uint4 v = make_uint4(0u, 0u, 0u, 0u);
        if (e < NE) v = *(const uint4*)&g_Wb[(size_t)e * KP + c8 * 8];
        *(uint4*)&sB[r * 216 + c8 * 8] = v;
    }
    __syncthreads();

    float acc[4][4][4];
#pragma unroll
    for (int a = 0; a < 4; a++)
#pragma unroll
        for (int b = 0; b < 4; b++)
#pragma unroll
            for (int c = 0; c < 4; c++) acc[a][b][c] = 0.f;

    const uint32_t* wA = (const uint32_t*)sA;   // 1 word = 2 bf16, row stride 108
    const uint32_t* wB = (const uint32_t*)sB;
#pragma unroll
    for (int kc = 0; kc < 13; ++kc) {
        uint32_t af[4][4];
#pragma unroll
        for (int mt = 0; mt < 4; ++mt) {
            const uint32_t* p = wA + (mw * 64 + mt * 16 + g) * 108 + kc * 8 + t;
            af[mt][0] = p[0];
            af[mt][1] = p[8 * 108];
            af[mt][2] = p[4];
            af[mt][3] = p[8 * 108 + 4];
        }
        uint32_t bfr[4][2];
#pragma unroll
        for (int nt = 0; nt < 4; ++nt) {
            const uint32_t* p = wB + (nw * 32 + nt * 8 + g) * 108 + kc * 8 + t;
            bfr[nt][0] = p[0];
            bfr[nt][1] = p[4];
        }
#pragma unroll
        for (int mt = 0; mt < 4; ++mt)
#pragma unroll
            for (int nt = 0; nt < 4; ++nt) {
                asm volatile(
                    "mma.sync.aligned.m16n8k16.row.col.f32.bf16.bf16.f32 "
                    "{%0,%1,%2,%3}, {%4,%5,%6,%7}, {%8,%9}, {%0,%1,%2,%3};\n"
                    : "+f"(acc[mt][nt][0]), "+f"(acc[mt][nt][1]),
                      "+f"(acc[mt][nt][2]), "+f"(acc[mt][nt][3])
                    : "r"(af[mt][0]), "r"(af[mt][1]), "r"(af[mt][2]), "r"(af[mt][3]),
                      "r"(bfr[nt][0]), "r"(bfr[nt][1]));
            }
    }

    // epilogue: exp(score + bias) -> scratch (|score|<0.2, no max-sub needed)
    float rsum[4][2];
#pragma unroll
    for (int mt = 0; mt < 4; ++mt) { rsum[mt][0] = 0.f; rsum[mt][1] = 0.f; }
#pragma unroll
    for (int mt = 0; mt < 4; ++mt) {
        int r0 = mblk + mw * 64 + mt * 16 + g;
#pragma unroll
        for (int nt = 0; nt < 4; ++nt) {
            int e0 = eblk + nw * 32 + nt * 8 + 2 * t;
            if (e0 < NE) {
                float b0v = bias[e0], b1v = bias[e0 + 1];
                float u0 = __expf(acc[mt][nt][0] + b0v);
                float u1 = __expf(acc[mt][nt][1] + b1v);
                float l0 = __expf(acc[mt][nt][2] + b0v);
                float l1 = __expf(acc[mt][nt][3] + b1v);
                *(float2*)&g_es[(size_t)r0 * NE + e0]       = make_float2(u0, u1);
                *(float2*)&g_es[(size_t)(r0 + 8) * NE + e0] = make_float2(l0, l1);
                rsum[mt][0] += u0 + u1;
                rsum[mt][1] += l0 + l1;
            }
        }
    }
    // deterministic per-row partial sums: reduce over t lanes, then over nw warps
#pragma unroll
    for (int mt = 0; mt < 4; ++mt) {
#pragma unroll
        for (int h = 0; h < 2; ++h) {
            float s = rsum[mt][h];
            s += __shfl_xor_sync(0xffffffffu, s, 1);
            s += __shfl_xor_sync(0xffffffffu, s, 2);
            if (t == 0) s_part[nw * 128 + mw * 64 + mt * 16 + h * 8 + g] = s;
        }
    }
    __syncthreads();
    if (tid < 128) {
        float s = s_part[tid] + s_part[128 + tid] + s_part[256 + tid] + s_part[384 + tid];
        g_part[(size_t)(mblk + tid) * GX + blockIdx.x] = s;
    }
}

// ---------------- K3b: reduce per-block partials -> 1/rowsum ------------------
__global__ void __launch_bounds__(128) k_rowsum()
{
    __shared__ float red[128];
    int row = blockIdx.x, tid = threadIdx.x;
    float s = 0.f;
    for (int i = tid; i < GX; i += 128) s += g_part[(size_t)row * GX + i];
    red[tid] = s; __syncthreads();
    for (int st = 64; st > 0; st >>= 1) {
        if (tid < st) red[tid] += red[tid + st];
        __syncthreads();
    }
    if (tid == 0) g_inv[row] = 1.0f / red[0];
}

// ---------------- K4: out = log(0.5*p_uniform + 0.5*sims) ---------------------
__global__ void __launch_bounds__(256) k_final(float* __restrict__ out)
{
    size_t i = (size_t)blockIdx.x * blockDim.x + threadIdx.x;   // float4 index
    int row = (int)(i / (NE / 4));
    float up  = 0.5f * g_up[row];
    float inv = 0.5f * g_inv[row];
    float4 v = *((const float4*)g_es + i);
    float4 o;
    o.x = __logf(fmaf(v.x, inv, up));
    o.y = __logf(fmaf(v.y, inv, up));
    o.z = __logf(fmaf(v.z, inv, up));
    o.w = __logf(fmaf(v.w, inv, up));
    ((float4*)out)[i] = o;
}

// ---------------- K5: fixup the <=50 scattered-p entries per row --------------
__global__ void __launch_bounds__(64) k_fix(const int* __restrict__ idx,
                                            float* __restrict__ out)
{
    int row = blockIdx.x, tid = threadIdx.x;
    if (tid < NH) {
        float pv = g_pval[row * NH + tid];
        if (pv >= 0.f) {
            int e = idx[row * NH + tid];
            float es = g_es[(size_t)row * NE + e];
            out[(size_t)row * NE + e] = __logf(0.5f * pv + 0.5f * es * g_inv[row]);
        }
    }
}

// ---------------- launch ------------------------------------------------------
extern "C" void kernel_launch(void* const* d_in, const int* in_sizes, int n_in,
                              void* d_out, int out_size)
{
    const int*   idx   = (const int*)d_in[0];
    const int*   times = (const int*)d_in[1];
    const float* emb   = (const float*)d_in[2];
    const float* Wsw   = (const float*)d_in[3];
    const float* Wsb   = (const float*)d_in[4];
    const float* mlpw  = (const float*)d_in[5];
    const float* mlpb  = (const float*)d_in[6];
    float*       out   = (float*)d_out;

    cudaFuncSetAttribute(k_routing, cudaFuncAttributeMaxDynamicSharedMemorySize, 55296);
    cudaFuncSetAttribute(k_gemm,    cudaFuncAttributeMaxDynamicSharedMemorySize, 112640);

    k_convw  <<<NE, 256>>>(mlpw);
    k_routing<<<BATCH, 256, 55296>>>(idx, times, emb, Wsw, Wsb);
    k_pprep  <<<BATCH, 64>>>(idx);
    k_gemm   <<<dim3(GX, BATCH / 128), 256, 112640>>>(mlpb);
    k_rowsum <<<BATCH, 128>>>();
    k_final  <<<(BATCH * NE / 4) / 256, 256>>>(out);   // 25000 blocks, exact cover
    k_fix    <<<BATCH, 64>>>(idx, out);
}